// round 14
// baseline (speedup 1.0000x reference)
#include <cuda_runtime.h>
#include <cuda_bf16.h>
#include <cuda_fp16.h>
#include <cstdint>

#define NN    50000
#define NNPAD 50048
#define NF    512
#define NHID  64
#define H1N   8
#define NC    16
#define NE    1600000
#define HID1  512   /* H1N*NHID */

// ---------------- scratch (device globals; no allocations allowed) ----------
__device__ __half g_h1h [(size_t)NN * HID1];
__device__ __half g_hp1h[(size_t)NN * HID1];
__device__ float g_ssrc1[NN * H1N];
__device__ float g_sdst1[NN * H1N];
__device__ float g_h2 [NN * NC];
__device__ float g_ss2[NN];
__device__ float g_sd2[NN];
__device__ int   g_deg[NN];
__device__ int   g_rowptr[NN + 1];
__device__ int   g_cursor[NN];
__device__ int   g_col[NE];
__device__ __nv_bfloat16 g_Xb[(size_t)NNPAD * NF];
__device__ __nv_bfloat16 g_Bb[HID1 * NF];   // [n][k] row-major

// ---------------- helpers ----------------
__device__ __forceinline__ uint32_t smem_u32(const void* p) {
    uint32_t a;
    asm("{ .reg .u64 t; cvta.to.shared.u64 t, %1; cvt.u32.u64 %0, t; }" : "=r"(a) : "l"(p));
    return a;
}
__device__ __forceinline__ void cp_async16(uint32_t dst, const void* src) {
    asm volatile("cp.async.cg.shared.global [%0], [%1], 16;" :: "r"(dst), "l"(src) : "memory");
}
__device__ __forceinline__ void cp_commit() {
    asm volatile("cp.async.commit_group;" ::: "memory");
}
template<int N>
__device__ __forceinline__ void cp_wait() {
    asm volatile("cp.async.wait_group %0;" :: "n"(N) : "memory");
}
__device__ __forceinline__ void ldsm4(uint32_t& r0, uint32_t& r1, uint32_t& r2, uint32_t& r3,
                                      uint32_t addr) {
    asm volatile("ldmatrix.sync.aligned.m8n8.x4.shared.b16 {%0,%1,%2,%3}, [%4];"
                 : "=r"(r0), "=r"(r1), "=r"(r2), "=r"(r3) : "r"(addr));
}
__device__ __forceinline__ void mma16816(float& c0, float& c1, float& c2, float& c3,
                                         uint32_t a0, uint32_t a1, uint32_t a2, uint32_t a3,
                                         uint32_t b0, uint32_t b1) {
    asm volatile("mma.sync.aligned.m16n8k16.row.col.f32.bf16.bf16.f32 "
                 "{%0,%1,%2,%3}, {%4,%5,%6,%7}, {%8,%9}, {%0,%1,%2,%3};"
                 : "+f"(c0), "+f"(c1), "+f"(c2), "+f"(c3)
                 : "r"(a0), "r"(a1), "r"(a2), "r"(a3), "r"(b0), "r"(b1));
}

// ---------------- GEMM tiling constants (128x64 tile, 3 CTAs/SM) ------------
#define BK 32
#define TSTRIDE 40
#define A_TILE_B (128 * TSTRIDE * 2)        /* 10240 */
#define B_TILE_B (64 * TSTRIDE * 2)         /* 5120 */
#define STAGE_B (A_TILE_B + B_TILE_B)       /* 15360 */
#define GEMM_SMEM (3 * STAGE_B)             /* 46080 */
#define BM_TILES 391                        /* NNPAD/128 */
#define BN_TILES 8                          /* 512/64 */
#define G_TILES  3128                       /* 391*8 */
#define GHALF    1564
#define CSRB     300

// ---------------- device bodies ----------------
__device__ void hist_body(const int* __restrict__ src) {
    for (int i = blockIdx.x * 256 + threadIdx.x; i < NE; i += CSRB * 256)
        atomicAdd(&g_deg[src[i]], 1);
}
__device__ void scatter_body(const int* __restrict__ src, const int* __restrict__ dst) {
    for (int i = blockIdx.x * 256 + threadIdx.x; i < NE; i += CSRB * 256) {
        int p = atomicAdd(&g_cursor[src[i]], 1);
        g_col[p] = dst[i];
    }
}

// 256-thread scan, 4 elems/thread; writes rowptr (inclusive,+1) + cursor (exclusive)
__device__ void scan_body(char* smem) {
    int* warpsums = (int*)smem;
    int* carry    = (int*)smem + 8;
    int t = threadIdx.x, lane = t & 31, wid = t >> 5;
    if (t == 0) { *carry = 0; g_rowptr[0] = 0; }
    __syncthreads();
    for (int base = 0; base < NN; base += 1024) {
        int idx0 = base + t * 4;
        int4 v = make_int4(0, 0, 0, 0);
        if (idx0 + 3 < NN) v = *(const int4*)(g_deg + idx0);
        else {
            if (idx0     < NN) v.x = g_deg[idx0];
            if (idx0 + 1 < NN) v.y = g_deg[idx0 + 1];
            if (idx0 + 2 < NN) v.z = g_deg[idx0 + 2];
        }
        int s1 = v.x + v.y, s2 = s1 + v.z, s3 = s2 + v.w;
        int x = s3;
        #pragma unroll
        for (int o = 1; o < 32; o <<= 1) {
            int y = __shfl_up_sync(0xffffffffu, x, o);
            if (lane >= o) x += y;
        }
        if (lane == 31) warpsums[wid] = x;
        __syncthreads();
        int carry_in = *carry;
        if (wid == 0) {
            int w = (lane < 8) ? warpsums[lane] : 0;
            #pragma unroll
            for (int o = 1; o < 8; o <<= 1) {
                int y = __shfl_up_sync(0xffffffffu, w, o);
                if (lane >= o) w += y;
            }
            if (lane < 8) warpsums[lane] = w;
        }
        __syncthreads();
        int warpoff = (wid > 0) ? warpsums[wid - 1] : 0;
        int excl = carry_in + warpoff + (x - s3);
        int i0 = excl + v.x, i1 = excl + s1, i2 = excl + s2, i3 = excl + s3;
        if (idx0     < NN) { g_rowptr[idx0 + 1] = i0; g_cursor[idx0]     = excl; }
        if (idx0 + 1 < NN) { g_rowptr[idx0 + 2] = i1; g_cursor[idx0 + 1] = i0; }
        if (idx0 + 2 < NN) { g_rowptr[idx0 + 3] = i2; g_cursor[idx0 + 2] = i1; }
        if (idx0 + 3 < NN) { g_rowptr[idx0 + 4] = i3; g_cursor[idx0 + 3] = i2; }
        __syncthreads();
        if (t == 255) *carry = excl + s3;
        __syncthreads();
    }
}

// GEMM tile body — 128x64 tile, warp grid 4x2 (warp tile 32x32), BK=32
__device__ void gemm_body(int tile, const float* __restrict__ a1) {
    extern __shared__ char smem[];
    const uint32_t sb = smem_u32(smem);
    const int tid = threadIdx.x;
    const int wid = tid >> 5, lane = tid & 31;
    const int wm = wid >> 1, wn = wid & 1;
    const int bm = (tile % BM_TILES) * 128;
    const int bn = (tile / BM_TILES) * 64;

    auto load_stage = [&](int s, int buf) {
        const int k0 = s * BK;
        const uint32_t st = sb + buf * STAGE_B;
        // A: 512 chunks of 16B (128 rows x 4), B: 256 chunks (64 rows x 4)
        #pragma unroll
        for (int i = 0; i < 2; i++) {
            int c = tid + i * 256;
            int row = c >> 2, sub = (c & 3) * 8;
            uint32_t soff = (row * TSTRIDE + sub) * 2;
            cp_async16(st + soff, g_Xb + (size_t)(bm + row) * NF + k0 + sub);
        }
        {
            int c = tid;
            int row = c >> 2, sub = (c & 3) * 8;
            uint32_t soff = (row * TSTRIDE + sub) * 2;
            cp_async16(st + A_TILE_B + soff, g_Bb + (size_t)(bn + row) * NF + k0 + sub);
        }
        cp_commit();
    };

    float acc[2][4][4];
    #pragma unroll
    for (int i = 0; i < 2; i++)
        #pragma unroll
        for (int j = 0; j < 4; j++)
            #pragma unroll
            for (int q = 0; q < 4; q++) acc[i][j][q] = 0.f;

    const uint32_t aRow = lane & 15;
    const uint32_t aCol = (lane & 16) >> 1;
    const uint32_t bRow = (lane & 7) + ((lane & 16) >> 1);
    const uint32_t bCol = (lane & 8) ? 8u : 0u;

    load_stage(0, 0);
    load_stage(1, 1);

    const int NSTAGE = NF / BK;   // 16
    for (int s = 0; s < NSTAGE; s++) {
        if (s + 1 < NSTAGE) cp_wait<1>(); else cp_wait<0>();
        __syncthreads();
        if (s + 2 < NSTAGE) load_stage(s + 2, (s + 2) % 3);

        const uint32_t st = sb + (s % 3) * STAGE_B;
        #pragma unroll
        for (int kk = 0; kk < 2; kk++) {
            const int k0 = kk * 16;
            uint32_t ah[2][4], bh[4][2];
            #pragma unroll
            for (int mt = 0; mt < 2; mt++) {
                uint32_t off = ((wm * 32 + mt * 16 + aRow) * TSTRIDE + k0 + aCol) * 2;
                ldsm4(ah[mt][0], ah[mt][1], ah[mt][2], ah[mt][3], st + off);
            }
            #pragma unroll
            for (int np = 0; np < 2; np++) {
                uint32_t off = ((wn * 32 + np * 16 + bRow) * TSTRIDE + k0 + bCol) * 2;
                ldsm4(bh[np*2][0], bh[np*2][1], bh[np*2+1][0], bh[np*2+1][1],
                      st + A_TILE_B + off);
            }
            #pragma unroll
            for (int mt = 0; mt < 2; mt++)
                #pragma unroll
                for (int nt = 0; nt < 4; nt++)
                    mma16816(acc[mt][nt][0], acc[mt][nt][1], acc[mt][nt][2], acc[mt][nt][3],
                             ah[mt][0], ah[mt][1], ah[mt][2], ah[mt][3], bh[nt][0], bh[nt][1]);
        }
    }

    // epilogue A: fp16 h1
    const int erow = (lane >> 2);
    const int ecol = (lane & 3) * 2;
    #pragma unroll
    for (int mt = 0; mt < 2; mt++) {
        int r0 = bm + wm * 32 + mt * 16 + erow;
        #pragma unroll
        for (int nt = 0; nt < 4; nt++) {
            int c = bn + wn * 32 + nt * 8 + ecol;
            if (r0 < NN) {
                __half2 p = __floats2half2_rn(acc[mt][nt][0], acc[mt][nt][1]);
                *(__half2*)(g_h1h + (size_t)r0 * HID1 + c) = p;
            }
            if (r0 + 8 < NN) {
                __half2 p = __floats2half2_rn(acc[mt][nt][2], acc[mt][nt][3]);
                *(__half2*)(g_h1h + (size_t)(r0 + 8) * HID1 + c) = p;
            }
        }
    }

    // epilogue B: fused attention-score partial dots (whole tile = one head)
    {
        const int h = bn >> 6;
        const int fbase = wn * 32;
        float asv[4][2], adv[4][2];
        #pragma unroll
        for (int nt = 0; nt < 4; nt++) {
            int f = fbase + nt * 8 + ecol;
            asv[nt][0] = __ldg(&a1[h * 128 + f]);
            asv[nt][1] = __ldg(&a1[h * 128 + f + 1]);
            adv[nt][0] = __ldg(&a1[h * 128 + 64 + f]);
            adv[nt][1] = __ldg(&a1[h * 128 + 64 + f + 1]);
        }
        #pragma unroll
        for (int mt = 0; mt < 2; mt++) {
            float ps0 = 0.f, pd0 = 0.f, ps8 = 0.f, pd8 = 0.f;
            #pragma unroll
            for (int nt = 0; nt < 4; nt++) {
                ps0 += acc[mt][nt][0] * asv[nt][0] + acc[mt][nt][1] * asv[nt][1];
                pd0 += acc[mt][nt][0] * adv[nt][0] + acc[mt][nt][1] * adv[nt][1];
                ps8 += acc[mt][nt][2] * asv[nt][0] + acc[mt][nt][3] * asv[nt][1];
                pd8 += acc[mt][nt][2] * adv[nt][0] + acc[mt][nt][3] * adv[nt][1];
            }
            #pragma unroll
            for (int o = 1; o <= 2; o <<= 1) {
                ps0 += __shfl_xor_sync(0xffffffffu, ps0, o);
                pd0 += __shfl_xor_sync(0xffffffffu, pd0, o);
                ps8 += __shfl_xor_sync(0xffffffffu, ps8, o);
                pd8 += __shfl_xor_sync(0xffffffffu, pd8, o);
            }
            if ((lane & 3) == 0) {
                int r0 = bm + wm * 32 + mt * 16 + erow;
                if (r0 < NN) {
                    atomicAdd(&g_ssrc1[r0 * H1N + h], ps0);
                    atomicAdd(&g_sdst1[r0 * H1N + h], pd0);
                }
                if (r0 + 8 < NN) {
                    atomicAdd(&g_ssrc1[(r0 + 8) * H1N + h], ps8);
                    atomicAdd(&g_sdst1[(r0 + 8) * H1N + h], pd8);
                }
            }
        }
    }
}

// ---------------- kernel 1: zero deg + score accumulators ----------------
__global__ void zero_kernel() {
    int i = blockIdx.x * blockDim.x + threadIdx.x;
    if (i < NN) g_deg[i] = 0;
    if (i < NN * H1N) { g_ssrc1[i] = 0.f; g_sdst1[i] = 0.f; }
}

// ---------------- kernel 2: hist ∥ convert_x ∥ convert_w --------------------
#define CXBLK 25024
#define CWBLK 1024
__global__ void ph_kernel(const float* __restrict__ X, const float* __restrict__ W,
                          const int* __restrict__ src) {
    int bx = blockIdx.x;
    if (bx < CSRB) { hist_body(src); return; }
    bx -= CSRB;
    if (bx < CXBLK) {
        size_t i = (size_t)bx * 256 + threadIdx.x;
        size_t base = i * 4;
        int row = (int)(base >> 9);
        float4 v = make_float4(0.f, 0.f, 0.f, 0.f);
        if (row < NN) v = *(const float4*)(X + base);
        __nv_bfloat16 h0 = __float2bfloat16_rn(v.x), h1 = __float2bfloat16_rn(v.y);
        __nv_bfloat16 h2 = __float2bfloat16_rn(v.z), h3 = __float2bfloat16_rn(v.w);
        uint2 ph;
        ph.x = ((uint32_t)__bfloat16_as_ushort(h1) << 16) | __bfloat16_as_ushort(h0);
        ph.y = ((uint32_t)__bfloat16_as_ushort(h3) << 16) | __bfloat16_as_ushort(h2);
        *(uint2*)(g_Xb + base) = ph;
    } else {
        int tid = (bx - CXBLK) * 256 + threadIdx.x;
        int k = tid >> 9, n = tid & 511;
        float w = W[(n >> 6) * (NF * NHID) + k * NHID + (n & 63)];
        g_Bb[n * NF + k] = __float2bfloat16_rn(w);
    }
}

// ---------------- kernel 3: scan ∥ gemm half A ----------------
__global__ __launch_bounds__(256, 3) void m3_kernel(const float* __restrict__ a1) {
    int bx = blockIdx.x;
    if (bx == 0) { extern __shared__ char smem[]; scan_body(smem); }
    else gemm_body(bx - 1, a1);
}
// ---------------- kernel 4: scatter ∥ gemm half B ----------------
__global__ __launch_bounds__(256, 3) void m4_kernel(const float* __restrict__ a1,
                                                    const int* __restrict__ src,
                                                    const int* __restrict__ dst) {
    int bx = blockIdx.x;
    if (bx < CSRB) scatter_body(src, dst);
    else gemm_body(GHALF + (bx - CSRB), a1);
}

// ---------------- layer-1 edge aggregation (lean) ----------------
__global__ __launch_bounds__(128) void agg1_kernel() {
    int n = blockIdx.x;
    int t = threadIdx.x;
    int head = t >> 4;
    int evh = t & 7;
    __shared__ int   sc[128];
    __shared__ float sev[128 * H1N];
    int beg = g_rowptr[n], end = g_rowptr[n + 1];
    float ssh = g_ssrc1[n * H1N + evh];
    float4 acc = make_float4(0.f, 0.f, 0.f, 0.f);
    float rsum = 0.f;
    int c0 = t * 4;
    for (int base = beg; base < end; base += 128) {
        int cnt = min(128, end - base);
        if (t < cnt) sc[t] = g_col[base + t];
        __syncthreads();
        for (int j0 = (t >> 3); j0 < cnt; j0 += 16) {
            int d = sc[j0];
            float lg = ssh + __ldg(&g_sdst1[d * H1N + evh]);
            float lr = lg > 0.f ? lg : 0.2f * lg;
            sev[j0 * H1N + evh] = __expf(-lr);
        }
        __syncthreads();
        int j = 0;
        for (; j + 4 <= cnt; j += 4) {
            int d0 = sc[j], d1 = sc[j+1], d2 = sc[j+2], d3 = sc[j+3];
            float e0 = sev[(j+0) * H1N + head];
            float e1 = sev[(j+1) * H1N + head];
            float e2 = sev[(j+2) * H1N + head];
            float e3 = sev[(j+3) * H1N + head];
            uint2 r0 = *(const uint2*)(g_h1h + (size_t)d0 * HID1 + c0);
            uint2 r1 = *(const uint2*)(g_h1h + (size_t)d1 * HID1 + c0);
            uint2 r2 = *(const uint2*)(g_h1h + (size_t)d2 * HID1 + c0);
            uint2 r3 = *(const uint2*)(g_h1h + (size_t)d3 * HID1 + c0);
            rsum += e0 + e1 + e2 + e3;
            float2 a, b;
            a = __half22float2(*(__half2*)&r0.x); b = __half22float2(*(__half2*)&r0.y);
            acc.x += e0 * a.x; acc.y += e0 * a.y; acc.z += e0 * b.x; acc.w += e0 * b.y;
            a = __half22float2(*(__half2*)&r1.x); b = __half22float2(*(__half2*)&r1.y);
            acc.x += e1 * a.x; acc.y += e1 * a.y; acc.z += e1 * b.x; acc.w += e1 * b.y;
            a = __half22float2(*(__half2*)&r2.x); b = __half22float2(*(__half2*)&r2.y);
            acc.x += e2 * a.x; acc.y += e2 * a.y; acc.z += e2 * b.x; acc.w += e2 * b.y;
            a = __half22float2(*(__half2*)&r3.x); b = __half22float2(*(__half2*)&r3.y);
            acc.x += e3 * a.x; acc.y += e3 * a.y; acc.z += e3 * b.x; acc.w += e3 * b.y;
        }
        for (; j < cnt; j++) {
            int d = sc[j];
            float ev = sev[j * H1N + head];
            rsum += ev;
            uint2 raw = *(const uint2*)(g_h1h + (size_t)d * HID1 + c0);
            float2 f01 = __half22float2(*(__half2*)&raw.x);
            float2 f23 = __half22float2(*(__half2*)&raw.y);
            acc.x += ev * f01.x; acc.y += ev * f01.y;
            acc.z += ev * f23.x; acc.w += ev * f23.y;
        }
        __syncthreads();
    }
    float inv = 1.f / rsum;
    float4 hp = make_float4(acc.x * inv, acc.y * inv, acc.z * inv, acc.w * inv);
    hp.x = hp.x > 0.f ? hp.x : (__expf(hp.x) - 1.f);
    hp.y = hp.y > 0.f ? hp.y : (__expf(hp.y) - 1.f);
    hp.z = hp.z > 0.f ? hp.z : (__expf(hp.z) - 1.f);
    hp.w = hp.w > 0.f ? hp.w : (__expf(hp.w) - 1.f);
    __half2 pa = __floats2half2_rn(hp.x, hp.y);
    __half2 pb = __floats2half2_rn(hp.z, hp.w);
    uint2 pk = make_uint2(*(uint32_t*)&pa, *(uint32_t*)&pb);
    *(uint2*)(g_hp1h + (size_t)n * HID1 + c0) = pk;
}

// ---------------- layer-2 GEMM (N=16) + scores (lean, separate) -------------
__global__ void l2_kernel(const float* __restrict__ W2, const float* __restrict__ a2) {
    int tid = blockIdx.x * blockDim.x + threadIdx.x;
    int n = tid >> 4, c = tid & 15;
    if (n >= NN) return;
    const __half* hrow = g_hp1h + (size_t)n * HID1;
    float acc = 0.f;
    for (int k = 0; k < HID1; k += 4) {
        uint2 raw = *(const uint2*)(hrow + k);
        float2 f01 = __half22float2(*(__half2*)&raw.x);
        float2 f23 = __half22float2(*(__half2*)&raw.y);
        acc += f01.x * W2[(k + 0) * NC + c];
        acc += f01.y * W2[(k + 1) * NC + c];
        acc += f23.x * W2[(k + 2) * NC + c];
        acc += f23.y * W2[(k + 3) * NC + c];
    }
    g_h2[n * NC + c] = acc;
    float ps = acc * a2[c], pd = acc * a2[NC + c];
    #pragma unroll
    for (int o = 8; o; o >>= 1) {
        ps += __shfl_xor_sync(0xffffffffu, ps, o, 16);
        pd += __shfl_xor_sync(0xffffffffu, pd, o, 16);
    }
    if (c == 0) { g_ss2[n] = ps; g_sd2[n] = pd; }
}

// ---------------- layer-2 aggregation + elu + log_softmax -------------------
__global__ void agg2_kernel(float* __restrict__ out) {
    int gw = (blockIdx.x * blockDim.x + threadIdx.x) >> 5;
    int lane = threadIdx.x & 31;
    if (gw >= NN) return;
    int n = gw;
    int beg = g_rowptr[n], end = g_rowptr[n + 1];
    float ss = g_ss2[n];
    float rsum = 0.f;
    float4 A0 = make_float4(0.f,0.f,0.f,0.f), A1 = A0, A2 = A0, A3 = A0;
    for (int e = beg + lane; e < end; e += 32) {
        int d = g_col[e];
        float lg = ss + __ldg(&g_sd2[d]);
        float lr = lg > 0.f ? lg : 0.2f * lg;
        float ev = __expf(-lr);
        rsum += ev;
        const float4* hp = (const float4*)(g_h2 + d * NC);
        float4 v0 = hp[0], v1 = hp[1], v2 = hp[2], v3 = hp[3];
        A0.x += ev*v0.x; A0.y += ev*v0.y; A0.z += ev*v0.z; A0.w += ev*v0.w;
        A1.x += ev*v1.x; A1.y += ev*v1.y; A1.z += ev*v1.z; A1.w += ev*v1.w;
        A2.x += ev*v2.x; A2.y += ev*v2.y; A2.z += ev*v2.z; A2.w += ev*v2.w;
        A3.x += ev*v3.x; A3.y += ev*v3.y; A3.z += ev*v3.z; A3.w += ev*v3.w;
    }
    #pragma unroll
    for (int o = 16; o; o >>= 1) {
        rsum += __shfl_xor_sync(0xffffffffu, rsum, o);
        A0.x += __shfl_xor_sync(0xffffffffu, A0.x, o);
        A0.y += __shfl_xor_sync(0xffffffffu, A0.y, o);
        A0.z += __shfl_xor_sync(0xffffffffu, A0.z, o);
        A0.w += __shfl_xor_sync(0xffffffffu, A0.w, o);
        A1.x += __shfl_xor_sync(0xffffffffu, A1.x, o);
        A1.y += __shfl_xor_sync(0xffffffffu, A1.y, o);
        A1.z += __shfl_xor_sync(0xffffffffu, A1.z, o);
        A1.w += __shfl_xor_sync(0xffffffffu, A1.w, o);
        A2.x += __shfl_xor_sync(0xffffffffu, A2.x, o);
        A2.y += __shfl_xor_sync(0xffffffffu, A2.y, o);
        A2.z += __shfl_xor_sync(0xffffffffu, A2.z, o);
        A2.w += __shfl_xor_sync(0xffffffffu, A2.w, o);
        A3.x += __shfl_xor_sync(0xffffffffu, A3.x, o);
        A3.y += __shfl_xor_sync(0xffffffffu, A3.y, o);
        A3.z += __shfl_xor_sync(0xffffffffu, A3.z, o);
        A3.w += __shfl_xor_sync(0xffffffffu, A3.w, o);
    }
    if (lane == 0) {
        float inv = 1.f / rsum;
        float e[16];
        e[0]=A0.x*inv; e[1]=A0.y*inv; e[2]=A0.z*inv; e[3]=A0.w*inv;
        e[4]=A1.x*inv; e[5]=A1.y*inv; e[6]=A1.z*inv; e[7]=A1.w*inv;
        e[8]=A2.x*inv; e[9]=A2.y*inv; e[10]=A2.z*inv; e[11]=A2.w*inv;
        e[12]=A3.x*inv; e[13]=A3.y*inv; e[14]=A3.z*inv; e[15]=A3.w*inv;
        float m = -1e30f;
        #pragma unroll
        for (int c = 0; c < 16; c++) {
            e[c] = e[c] > 0.f ? e[c] : (__expf(e[c]) - 1.f);
            m = fmaxf(m, e[c]);
        }
        float s = 0.f;
        #pragma unroll
        for (int c = 0; c < 16; c++) s += __expf(e[c] - m);
        float lse = m + __logf(s);
        float* o = out + (size_t)n * NC;
        *(float4*)(o + 0)  = make_float4(e[0]-lse, e[1]-lse, e[2]-lse, e[3]-lse);
        *(float4*)(o + 4)  = make_float4(e[4]-lse, e[5]-lse, e[6]-lse, e[7]-lse);
        *(float4*)(o + 8)  = make_float4(e[8]-lse, e[9]-lse, e[10]-lse, e[11]-lse);
        *(float4*)(o + 12) = make_float4(e[12]-lse, e[13]-lse, e[14]-lse, e[15]-lse);
    }
}

// ---------------- launch ----------------
extern "C" void kernel_launch(void* const* d_in, const int* in_sizes, int n_in,
                              void* d_out, int out_size) {
    const float* x  = (const float*)d_in[0];
    const int*   ei = (const int*)d_in[1];
    const float* W1 = (const float*)d_in[2];
    const float* a1 = (const float*)d_in[3];
    const float* W2 = (const float*)d_in[4];
    const float* a2 = (const float*)d_in[5];
    float* out = (float*)d_out;
    const int* src = ei;
    const int* dst = ei + NE;

    cudaFuncSetAttribute(m3_kernel, cudaFuncAttributeMaxDynamicSharedMemorySize, GEMM_SMEM);
    cudaFuncSetAttribute(m4_kernel, cudaFuncAttributeMaxDynamicSharedMemorySize, GEMM_SMEM);

    zero_kernel<<<(NN * H1N + 255) / 256, 256>>>();
    ph_kernel<<<CSRB + CXBLK + CWBLK, 256>>>(x, W1, src);
    m3_kernel<<<1 + GHALF, 256, GEMM_SMEM>>>(a1);
    m4_kernel<<<CSRB + (G_TILES - GHALF), 256, GEMM_SMEM>>>(a1, src, dst);

    agg1_kernel<<<NN, 128>>>();
    l2_kernel<<<(NN * 16 + 255) / 256, 256>>>(W2, a2);
    agg2_kernel<<<(NN * 32 + 255) / 256, 256>>>(out);
}

// round 17
// speedup vs baseline: 1.0510x; 1.0510x over previous
#include <cuda_runtime.h>
#include <cuda_bf16.h>
#include <cuda_fp16.h>
#include <cstdint>

#define NN    50000
#define NNPAD 50048
#define NF    512
#define NHID  64
#define H1N   8
#define NC    16
#define NE    1600000
#define HID1  512   /* H1N*NHID */

// ---------------- scratch (device globals; no allocations allowed) ----------
__device__ __half g_h1h [(size_t)NN * HID1];
__device__ __half g_hp1h[(size_t)NN * HID1];
__device__ float g_ssrc1[NN * H1N];
__device__ float g_sdst1[NN * H1N];
__device__ float g_h2 [NN * NC];
__device__ float g_ss2[NN];
__device__ float g_sd2[NN];
__device__ int   g_deg[NN];
__device__ int   g_rowptr[NN + 1];
__device__ int   g_cursor[NN];
__device__ int   g_col[NE];
__device__ __nv_bfloat16 g_Xb[(size_t)NNPAD * NF];
__device__ __nv_bfloat16 g_Bb[HID1 * NF];   // [n][k] row-major

// ---------------- helpers ----------------
__device__ __forceinline__ uint32_t smem_u32(const void* p) {
    uint32_t a;
    asm("{ .reg .u64 t; cvta.to.shared.u64 t, %1; cvt.u32.u64 %0, t; }" : "=r"(a) : "l"(p));
    return a;
}
__device__ __forceinline__ void cp_async16(uint32_t dst, const void* src) {
    asm volatile("cp.async.cg.shared.global [%0], [%1], 16;" :: "r"(dst), "l"(src) : "memory");
}
__device__ __forceinline__ void cp_commit() {
    asm volatile("cp.async.commit_group;" ::: "memory");
}
template<int N>
__device__ __forceinline__ void cp_wait() {
    asm volatile("cp.async.wait_group %0;" :: "n"(N) : "memory");
}
__device__ __forceinline__ void ldsm4(uint32_t& r0, uint32_t& r1, uint32_t& r2, uint32_t& r3,
                                      uint32_t addr) {
    asm volatile("ldmatrix.sync.aligned.m8n8.x4.shared.b16 {%0,%1,%2,%3}, [%4];"
                 : "=r"(r0), "=r"(r1), "=r"(r2), "=r"(r3) : "r"(addr));
}
__device__ __forceinline__ void mma16816(float& c0, float& c1, float& c2, float& c3,
                                         uint32_t a0, uint32_t a1, uint32_t a2, uint32_t a3,
                                         uint32_t b0, uint32_t b1) {
    asm volatile("mma.sync.aligned.m16n8k16.row.col.f32.bf16.bf16.f32 "
                 "{%0,%1,%2,%3}, {%4,%5,%6,%7}, {%8,%9}, {%0,%1,%2,%3};"
                 : "+f"(c0), "+f"(c1), "+f"(c2), "+f"(c3)
                 : "r"(a0), "r"(a1), "r"(a2), "r"(a3), "r"(b0), "r"(b1));
}

// ---------------- GEMM tiling constants (R12 proven config) -----------------
#define BK 32
#define TSTRIDE 40
#define TILE_B (128 * TSTRIDE * 2)
#define STAGE_B (2 * TILE_B)
#define GEMM_SMEM (3 * STAGE_B)            /* 61440 */
#define BM_TILES 391                        /* NNPAD/128 */
#define G_TILES  1564                       /* 391*4 */
#define GHALF    782
#define CSRB     300

// ---------------- device bodies ----------------
__device__ void hist_body(const int* __restrict__ src) {
    for (int i = blockIdx.x * 256 + threadIdx.x; i < NE; i += CSRB * 256)
        atomicAdd(&g_deg[src[i]], 1);
}
__device__ void scatter_body(const int* __restrict__ src, const int* __restrict__ dst) {
    for (int i = blockIdx.x * 256 + threadIdx.x; i < NE; i += CSRB * 256) {
        int p = atomicAdd(&g_cursor[src[i]], 1);
        g_col[p] = dst[i];
    }
}

// 256-thread scan, 4 elems/thread; writes rowptr (inclusive,+1) + cursor (exclusive)
__device__ void scan_body(char* smem) {
    int* warpsums = (int*)smem;
    int* carry    = (int*)smem + 8;
    int t = threadIdx.x, lane = t & 31, wid = t >> 5;
    if (t == 0) { *carry = 0; g_rowptr[0] = 0; }
    __syncthreads();
    for (int base = 0; base < NN; base += 1024) {
        int idx0 = base + t * 4;
        int4 v = make_int4(0, 0, 0, 0);
        if (idx0 + 3 < NN) v = *(const int4*)(g_deg + idx0);
        else {
            if (idx0     < NN) v.x = g_deg[idx0];
            if (idx0 + 1 < NN) v.y = g_deg[idx0 + 1];
            if (idx0 + 2 < NN) v.z = g_deg[idx0 + 2];
        }
        int s1 = v.x + v.y, s2 = s1 + v.z, s3 = s2 + v.w;
        int x = s3;
        #pragma unroll
        for (int o = 1; o < 32; o <<= 1) {
            int y = __shfl_up_sync(0xffffffffu, x, o);
            if (lane >= o) x += y;
        }
        if (lane == 31) warpsums[wid] = x;
        __syncthreads();
        int carry_in = *carry;
        if (wid == 0) {
            int w = (lane < 8) ? warpsums[lane] : 0;
            #pragma unroll
            for (int o = 1; o < 8; o <<= 1) {
                int y = __shfl_up_sync(0xffffffffu, w, o);
                if (lane >= o) w += y;
            }
            if (lane < 8) warpsums[lane] = w;
        }
        __syncthreads();
        int warpoff = (wid > 0) ? warpsums[wid - 1] : 0;
        int excl = carry_in + warpoff + (x - s3);
        int i0 = excl + v.x, i1 = excl + s1, i2 = excl + s2, i3 = excl + s3;
        if (idx0     < NN) { g_rowptr[idx0 + 1] = i0; g_cursor[idx0]     = excl; }
        if (idx0 + 1 < NN) { g_rowptr[idx0 + 2] = i1; g_cursor[idx0 + 1] = i0; }
        if (idx0 + 2 < NN) { g_rowptr[idx0 + 3] = i2; g_cursor[idx0 + 2] = i1; }
        if (idx0 + 3 < NN) { g_rowptr[idx0 + 4] = i3; g_cursor[idx0 + 3] = i2; }
        __syncthreads();
        if (t == 255) *carry = excl + s3;
        __syncthreads();
    }
}

// GEMM tile body — R12 config: 128x128, BK=32, single barrier per stage
__device__ void gemm_body(int tile, const float* __restrict__ a1) {
    extern __shared__ char smem[];
    const uint32_t sb = smem_u32(smem);
    const int tid = threadIdx.x;
    const int wid = tid >> 5, lane = tid & 31;
    const int wm = wid >> 2, wn = wid & 3;
    const int bm = (tile % BM_TILES) * 128;
    const int bn = (tile / BM_TILES) * 128;

    const int ldRow0 = tid >> 2;
    const int ldCol  = (tid & 3) * 8;

    auto load_stage = [&](int s, int buf) {
        const int k0 = s * BK;
        const uint32_t st = sb + buf * STAGE_B;
        #pragma unroll
        for (int i = 0; i < 2; i++) {
            int row = ldRow0 + i * 64;
            uint32_t soff = (row * TSTRIDE + ldCol) * 2;
            cp_async16(st + 0 * TILE_B + soff, g_Xb + (size_t)(bm + row) * NF + k0 + ldCol);
            cp_async16(st + 1 * TILE_B + soff, g_Bb + (size_t)(bn + row) * NF + k0 + ldCol);
        }
        cp_commit();
    };

    float acc[4][4][4];
    #pragma unroll
    for (int i = 0; i < 4; i++)
        #pragma unroll
        for (int j = 0; j < 4; j++)
            #pragma unroll
            for (int q = 0; q < 4; q++) acc[i][j][q] = 0.f;

    const uint32_t aRow = lane & 15;
    const uint32_t aCol = (lane & 16) >> 1;
    const uint32_t bRow = (lane & 7) + ((lane & 16) >> 1);
    const uint32_t bCol = (lane & 8) ? 8u : 0u;

    load_stage(0, 0);
    load_stage(1, 1);

    const int NSTAGE = NF / BK;   // 16
    for (int s = 0; s < NSTAGE; s++) {
        if (s + 1 < NSTAGE) cp_wait<1>(); else cp_wait<0>();
        __syncthreads();
        if (s + 2 < NSTAGE) load_stage(s + 2, (s + 2) % 3);

        const uint32_t st = sb + (s % 3) * STAGE_B;
        #pragma unroll
        for (int kk = 0; kk < 2; kk++) {
            const int k0 = kk * 16;
            uint32_t ah[4][4], bh[4][2];
            #pragma unroll
            for (int mt = 0; mt < 4; mt++) {
                uint32_t off = ((wm * 64 + mt * 16 + aRow) * TSTRIDE + k0 + aCol) * 2;
                ldsm4(ah[mt][0], ah[mt][1], ah[mt][2], ah[mt][3], st + 0 * TILE_B + off);
            }
            #pragma unroll
            for (int np = 0; np < 2; np++) {
                uint32_t off = ((wn * 32 + np * 16 + bRow) * TSTRIDE + k0 + bCol) * 2;
                ldsm4(bh[np*2][0], bh[np*2][1], bh[np*2+1][0], bh[np*2+1][1],
                      st + 1 * TILE_B + off);
            }
            #pragma unroll
            for (int mt = 0; mt < 4; mt++)
                #pragma unroll
                for (int nt = 0; nt < 4; nt++)
                    mma16816(acc[mt][nt][0], acc[mt][nt][1], acc[mt][nt][2], acc[mt][nt][3],
                             ah[mt][0], ah[mt][1], ah[mt][2], ah[mt][3], bh[nt][0], bh[nt][1]);
        }
    }

    // epilogue A: fp16 h1
    const int erow = (lane >> 2);
    const int ecol = (lane & 3) * 2;
    #pragma unroll
    for (int mt = 0; mt < 4; mt++) {
        int r0 = bm + wm * 64 + mt * 16 + erow;
        #pragma unroll
        for (int nt = 0; nt < 4; nt++) {
            int c = bn + wn * 32 + nt * 8 + ecol;
            if (r0 < NN) {
                __half2 p = __floats2half2_rn(acc[mt][nt][0], acc[mt][nt][1]);
                *(__half2*)(g_h1h + (size_t)r0 * HID1 + c) = p;
            }
            if (r0 + 8 < NN) {
                __half2 p = __floats2half2_rn(acc[mt][nt][2], acc[mt][nt][3]);
                *(__half2*)(g_h1h + (size_t)(r0 + 8) * HID1 + c) = p;
            }
        }
    }

    // epilogue B: fused attention-score partial dots
    {
        const int h = (bn >> 6) + (wn >> 1);
        const int fbase = (wn & 1) * 32;
        float asv[4][2], adv[4][2];
        #pragma unroll
        for (int nt = 0; nt < 4; nt++) {
            int f = fbase + nt * 8 + ecol;
            asv[nt][0] = __ldg(&a1[h * 128 + f]);
            asv[nt][1] = __ldg(&a1[h * 128 + f + 1]);
            adv[nt][0] = __ldg(&a1[h * 128 + 64 + f]);
            adv[nt][1] = __ldg(&a1[h * 128 + 64 + f + 1]);
        }
        #pragma unroll
        for (int mt = 0; mt < 4; mt++) {
            float ps0 = 0.f, pd0 = 0.f, ps8 = 0.f, pd8 = 0.f;
            #pragma unroll
            for (int nt = 0; nt < 4; nt++) {
                ps0 += acc[mt][nt][0] * asv[nt][0] + acc[mt][nt][1] * asv[nt][1];
                pd0 += acc[mt][nt][0] * adv[nt][0] + acc[mt][nt][1] * adv[nt][1];
                ps8 += acc[mt][nt][2] * asv[nt][0] + acc[mt][nt][3] * asv[nt][1];
                pd8 += acc[mt][nt][2] * adv[nt][0] + acc[mt][nt][3] * adv[nt][1];
            }
            #pragma unroll
            for (int o = 1; o <= 2; o <<= 1) {
                ps0 += __shfl_xor_sync(0xffffffffu, ps0, o);
                pd0 += __shfl_xor_sync(0xffffffffu, pd0, o);
                ps8 += __shfl_xor_sync(0xffffffffu, ps8, o);
                pd8 += __shfl_xor_sync(0xffffffffu, pd8, o);
            }
            if ((lane & 3) == 0) {
                int r0 = bm + wm * 64 + mt * 16 + erow;
                if (r0 < NN) {
                    atomicAdd(&g_ssrc1[r0 * H1N + h], ps0);
                    atomicAdd(&g_sdst1[r0 * H1N + h], pd0);
                }
                if (r0 + 8 < NN) {
                    atomicAdd(&g_ssrc1[(r0 + 8) * H1N + h], ps8);
                    atomicAdd(&g_sdst1[(r0 + 8) * H1N + h], pd8);
                }
            }
        }
    }
}

// ---------------- kernel 1: zero deg + score accumulators ----------------
__global__ void zero_kernel() {
    int i = blockIdx.x * blockDim.x + threadIdx.x;
    if (i < NN) g_deg[i] = 0;
    if (i < NN * H1N) { g_ssrc1[i] = 0.f; g_sdst1[i] = 0.f; }
}

// ---------------- kernel 2: hist ∥ convert_x ∥ convert_w --------------------
#define CXBLK 25024
#define CWBLK 1024
__global__ void ph_kernel(const float* __restrict__ X, const float* __restrict__ W,
                          const int* __restrict__ src) {
    int bx = blockIdx.x;
    if (bx < CSRB) { hist_body(src); return; }
    bx -= CSRB;
    if (bx < CXBLK) {
        size_t i = (size_t)bx * 256 + threadIdx.x;
        size_t base = i * 4;
        int row = (int)(base >> 9);
        float4 v = make_float4(0.f, 0.f, 0.f, 0.f);
        if (row < NN) v = *(const float4*)(X + base);
        __nv_bfloat16 h0 = __float2bfloat16_rn(v.x), h1 = __float2bfloat16_rn(v.y);
        __nv_bfloat16 h2 = __float2bfloat16_rn(v.z), h3 = __float2bfloat16_rn(v.w);
        uint2 ph;
        ph.x = ((uint32_t)__bfloat16_as_ushort(h1) << 16) | __bfloat16_as_ushort(h0);
        ph.y = ((uint32_t)__bfloat16_as_ushort(h3) << 16) | __bfloat16_as_ushort(h2);
        *(uint2*)(g_Xb + base) = ph;
    } else {
        int tid = (bx - CXBLK) * 256 + threadIdx.x;
        int k = tid >> 9, n = tid & 511;
        float w = W[(n >> 6) * (NF * NHID) + k * NHID + (n & 63)];
        g_Bb[n * NF + k] = __float2bfloat16_rn(w);
    }
}

// ---------------- kernel 3: scan ∥ gemm half A ----------------
__global__ __launch_bounds__(256, 2) void m3_kernel(const float* __restrict__ a1) {
    int bx = blockIdx.x;
    if (bx == 0) { extern __shared__ char smem[]; scan_body(smem); }
    else gemm_body(bx - 1, a1);
}
// ---------------- kernel 4: scatter ∥ gemm half B ----------------
__global__ __launch_bounds__(256, 2) void m4_kernel(const float* __restrict__ a1,
                                                    const int* __restrict__ src,
                                                    const int* __restrict__ dst) {
    int bx = blockIdx.x;
    if (bx < CSRB) scatter_body(src, dst);
    else gemm_body(GHALF + (bx - CSRB), a1);
}

// ---------------- layer-1 edge aggregation (uint4, 2 edges/block-iter) ------
__global__ __launch_bounds__(128) void agg1_kernel() {
    int n = blockIdx.x;
    int t = threadIdx.x;
    int ft  = t & 63;            // feature-thread: owns 8 feats of one head
    int grp = t >> 6;            // 0 -> even edges, 1 -> odd edges
    int head = ft >> 3;
    int evh = t & 7;
    __shared__ int   sc[128];
    __shared__ float sev[128 * H1N];
    __shared__ float smerge[64 * 9];
    int beg = g_rowptr[n], end = g_rowptr[n + 1];
    float ssh = g_ssrc1[n * H1N + evh];
    float acc[8] = {0.f, 0.f, 0.f, 0.f, 0.f, 0.f, 0.f, 0.f};
    float rsum = 0.f;
    int c0 = ft * 8;
    for (int base = beg; base < end; base += 128) {
        int cnt = min(128, end - base);
        if (t < cnt) sc[t] = g_col[base + t];
        __syncthreads();
        for (int j0 = (t >> 3); j0 < cnt; j0 += 16) {
            int d = sc[j0];
            float lg = ssh + __ldg(&g_sdst1[d * H1N + evh]);
            float lr = lg > 0.f ? lg : 0.2f * lg;
            sev[j0 * H1N + evh] = __expf(-lr);
        }
        __syncthreads();
        int j = grp;
        for (; j + 2 < cnt; j += 4) {            // 2 edges of my parity per iter
            int d0 = sc[j], d1 = sc[j + 2];
            float e0 = sev[j * H1N + head];
            float e1 = sev[(j + 2) * H1N + head];
            uint4 r0 = *(const uint4*)(g_h1h + (size_t)d0 * HID1 + c0);
            uint4 r1 = *(const uint4*)(g_h1h + (size_t)d1 * HID1 + c0);
            rsum += e0 + e1;
            float2 f;
            f = __half22float2(*(__half2*)&r0.x); acc[0]+=e0*f.x; acc[1]+=e0*f.y;
            f = __half22float2(*(__half2*)&r0.y); acc[2]+=e0*f.x; acc[3]+=e0*f.y;
            f = __half22float2(*(__half2*)&r0.z); acc[4]+=e0*f.x; acc[5]+=e0*f.y;
            f = __half22float2(*(__half2*)&r0.w); acc[6]+=e0*f.x; acc[7]+=e0*f.y;
            f = __half22float2(*(__half2*)&r1.x); acc[0]+=e1*f.x; acc[1]+=e1*f.y;
            f = __half22float2(*(__half2*)&r1.y); acc[2]+=e1*f.x; acc[3]+=e1*f.y;
            f = __half22float2(*(__half2*)&r1.z); acc[4]+=e1*f.x; acc[5]+=e1*f.y;
            f = __half22float2(*(__half2*)&r1.w); acc[6]+=e1*f.x; acc[7]+=e1*f.y;
        }
        for (; j < cnt; j += 2) {
            int d = sc[j];
            float ev = sev[j * H1N + head];
            uint4 raw = *(const uint4*)(g_h1h + (size_t)d * HID1 + c0);
            rsum += ev;
            float2 f;
            f = __half22float2(*(__half2*)&raw.x); acc[0]+=ev*f.x; acc[1]+=ev*f.y;
            f = __half22float2(*(__half2*)&raw.y); acc[2]+=ev*f.x; acc[3]+=ev*f.y;
            f = __half22float2(*(__half2*)&raw.z); acc[4]+=ev*f.x; acc[5]+=ev*f.y;
            f = __half22float2(*(__half2*)&raw.w); acc[6]+=ev*f.x; acc[7]+=ev*f.y;
        }
        __syncthreads();
    }
    // merge the two edge-parity groups
    if (grp == 1) {
        #pragma unroll
        for (int q = 0; q < 8; q++) smerge[ft * 9 + q] = acc[q];
        smerge[ft * 9 + 8] = rsum;
    }
    __syncthreads();
    if (grp == 0) {
        #pragma unroll
        for (int q = 0; q < 8; q++) acc[q] += smerge[ft * 9 + q];
        rsum += smerge[ft * 9 + 8];
        float inv = 1.f / rsum;
        __half hh[8];
        #pragma unroll
        for (int q = 0; q < 8; q++) {
            float v = acc[q] * inv;
            v = v > 0.f ? v : (__expf(v) - 1.f);
            hh[q] = __float2half_rn(v);
        }
        *(uint4*)(g_hp1h + (size_t)n * HID1 + c0) = *(uint4*)hh;
    }
}

// ---------------- layer-2 GEMM (N=16) + scores (lean, separate) -------------
__global__ void l2_kernel(const float* __restrict__ W2, const float* __restrict__ a2) {
    int tid = blockIdx.x * blockDim.x + threadIdx.x;
    int n = tid >> 4, c = tid & 15;
    if (n >= NN) return;
    const __half* hrow = g_hp1h + (size_t)n * HID1;
    float acc = 0.f;
    for (int k = 0; k < HID1; k += 4) {
        uint2 raw = *(const uint2*)(hrow + k);
        float2 f01 = __half22float2(*(__half2*)&raw.x);
        float2 f23 = __half22float2(*(__half2*)&raw.y);
        acc += f01.x * W2[(k + 0) * NC + c];
        acc += f01.y * W2[(k + 1) * NC + c];
        acc += f23.x * W2[(k + 2) * NC + c];
        acc += f23.y * W2[(k + 3) * NC + c];
    }
    g_h2[n * NC + c] = acc;
    float ps = acc * a2[c], pd = acc * a2[NC + c];
    #pragma unroll
    for (int o = 8; o; o >>= 1) {
        ps += __shfl_xor_sync(0xffffffffu, ps, o, 16);
        pd += __shfl_xor_sync(0xffffffffu, pd, o, 16);
    }
    if (c == 0) { g_ss2[n] = ps; g_sd2[n] = pd; }
}

// ---------------- layer-2 aggregation + elu + log_softmax -------------------
__global__ void agg2_kernel(float* __restrict__ out) {
    int gw = (blockIdx.x * blockDim.x + threadIdx.x) >> 5;
    int lane = threadIdx.x & 31;
    if (gw >= NN) return;
    int n = gw;
    int beg = g_rowptr[n], end = g_rowptr[n + 1];
    float ss = g_ss2[n];
    float rsum = 0.f;
    float4 A0 = make_float4(0.f,0.f,0.f,0.f), A1 = A0, A2 = A0, A3 = A0;
    for (int e = beg + lane; e < end; e += 32) {
        int d = g_col[e];
        float lg = ss + __ldg(&g_sd2[d]);
        float lr = lg > 0.f ? lg : 0.2f * lg;
        float ev = __expf(-lr);
        rsum += ev;
        const float4* hp = (const float4*)(g_h2 + d * NC);
        float4 v0 = hp[0], v1 = hp[1], v2 = hp[2], v3 = hp[3];
        A0.x += ev*v0.x; A0.y += ev*v0.y; A0.z += ev*v0.z; A0.w += ev*v0.w;
        A1.x += ev*v1.x; A1.y += ev*v1.y; A1.z += ev*v1.z; A1.w += ev*v1.w;
        A2.x += ev*v2.x; A2.y += ev*v2.y; A2.z += ev*v2.z; A2.w += ev*v2.w;
        A3.x += ev*v3.x; A3.y += ev*v3.y; A3.z += ev*v3.z; A3.w += ev*v3.w;
    }
    #pragma unroll
    for (int o = 16; o; o >>= 1) {
        rsum += __shfl_xor_sync(0xffffffffu, rsum, o);
        A0.x += __shfl_xor_sync(0xffffffffu, A0.x, o);
        A0.y += __shfl_xor_sync(0xffffffffu, A0.y, o);
        A0.z += __shfl_xor_sync(0xffffffffu, A0.z, o);
        A0.w += __shfl_xor_sync(0xffffffffu, A0.w, o);
        A1.x += __shfl_xor_sync(0xffffffffu, A1.x, o);
        A1.y += __shfl_xor_sync(0xffffffffu, A1.y, o);
        A1.z += __shfl_xor_sync(0xffffffffu, A1.z, o);
        A1.w += __shfl_xor_sync(0xffffffffu, A1.w, o);
        A2.x += __shfl_xor_sync(0xffffffffu, A2.x, o);
        A2.y += __shfl_xor_sync(0xffffffffu, A2.y, o);
        A2.z += __shfl_xor_sync(0xffffffffu, A2.z, o);
        A2.w += __shfl_xor_sync(0xffffffffu, A2.w, o);
        A3.x += __shfl_xor_sync(0xffffffffu, A3.x, o);
        A3.y += __shfl_xor_sync(0xffffffffu, A3.y, o);
        A3.z += __shfl_xor_sync(0xffffffffu, A3.z, o);
        A3.w += __shfl_xor_sync(0xffffffffu, A3.w, o);
    }
    if (lane == 0) {
        float inv = 1.f / rsum;
        float e[16];
        e[0]=A0.x*inv; e[1]=A0.y*inv; e[2]=A0.z*inv; e[3]=A0.w*inv;
        e[4]=A1.x*inv; e[5]=A1.y*inv; e[6]=A1.z*inv; e[7]=A1.w*inv;
        e[8]=A2.x*inv; e[9]=A2.y*inv; e[10]=A2.z*inv; e[11]=A2.w*inv;
        e[12]=A3.x*inv; e[13]=A3.y*inv; e[14]=A3.z*inv; e[15]=A3.w*inv;
        float m = -1e30f;
        #pragma unroll
        for (int c = 0; c < 16; c++) {
            e[c] = e[c] > 0.f ? e[c] : (__expf(e[c]) - 1.f);
            m = fmaxf(m, e[c]);
        }
        float s = 0.f;
        #pragma unroll
        for (int c = 0; c < 16; c++) s += __expf(e[c] - m);
        float lse = m + __logf(s);
        float* o = out + (size_t)n * NC;
        *(float4*)(o + 0)  = make_float4(e[0]-lse, e[1]-lse, e[2]-lse, e[3]-lse);
        *(float4*)(o + 4)  = make_float4(e[4]-lse, e[5]-lse, e[6]-lse, e[7]-lse);
        *(float4*)(o + 8)  = make_float4(e[8]-lse, e[9]-lse, e[10]-lse, e[11]-lse);
        *(float4*)(o + 12) = make_float4(e[12]-lse, e[13]-lse, e[14]-lse, e[15]-lse);
    }
}

// ---------------- launch ----------------
extern "C" void kernel_launch(void* const* d_in, const int* in_sizes, int n_in,
                              void* d_out, int out_size) {
    const float* x  = (const float*)d_in[0];
    const int*   ei = (const int*)d_in[1];
    const float* W1 = (const float*)d_in[2];
    const float* a1 = (const float*)d_in[3];
    const float* W2 = (const float*)d_in[4];
    const float* a2 = (const float*)d_in[5];
    float* out = (float*)d_out;
    const int* src = ei;
    const int* dst = ei + NE;

    cudaFuncSetAttribute(m3_kernel, cudaFuncAttributeMaxDynamicSharedMemorySize, GEMM_SMEM);
    cudaFuncSetAttribute(m4_kernel, cudaFuncAttributeMaxDynamicSharedMemorySize, GEMM_SMEM);

    zero_kernel<<<(NN * H1N + 255) / 256, 256>>>();
    ph_kernel<<<CSRB + CXBLK + CWBLK, 256>>>(x, W1, src);
    m3_kernel<<<1 + GHALF, 256, GEMM_SMEM>>>(a1);
    m4_kernel<<<CSRB + (G_TILES - GHALF), 256, GEMM_SMEM>>>(a1, src, dst);

    agg1_kernel<<<NN, 128>>>();
    l2_kernel<<<(NN * 16 + 255) / 256, 256>>>(W2, a2);
    agg2_kernel<<<(NN * 32 + 255) / 256, 256>>>(out);
}